// round 5
// baseline (speedup 1.0000x reference)
#include <cuda_runtime.h>

typedef unsigned long long u64;

// ---------------------------------------------------------------------------
// Static device scratch. Projection tables padded to 16 floats/row (64B) so
// every row lies entirely inside ONE 128B line (64B-aligned, 40B of data).
// ---------------------------------------------------------------------------
#define NS_MAX 100000
#define NT_MAX 100000
#define BB_MAX 10000

__device__ __align__(16) float g_Ps[NS_MAX * 16];
__device__ __align__(16) float g_Pt[NT_MAX * 16];
__device__ __align__(16) float g_Pu[BB_MAX * 16];

// ---------------------------------------------------------------------------
// Packed f32x2 helpers (Blackwell sm_103a; ptxas never auto-fuses these).
// ---------------------------------------------------------------------------
__device__ __forceinline__ u64 pk2(float lo, float hi) {
    u64 r; asm("mov.b64 %0, {%1, %2};" : "=l"(r) : "f"(lo), "f"(hi)); return r;
}
__device__ __forceinline__ void upk2(u64 v, float& lo, float& hi) {
    asm("mov.b64 {%0, %1}, %2;" : "=f"(lo), "=f"(hi) : "l"(v));
}
__device__ __forceinline__ u64 fma2(u64 a, u64 b, u64 c) {
    u64 d; asm("fma.rn.f32x2 %0, %1, %2, %3;" : "=l"(d) : "l"(a), "l"(b), "l"(c)); return d;
}
__device__ __forceinline__ u64 add2(u64 a, u64 b) {
    u64 d; asm("add.rn.f32x2 %0, %1, %2;" : "=l"(d) : "l"(a), "l"(b)); return d;
}

// ---------------------------------------------------------------------------
// Fused projection kernel (one launch for all three tables).
// out[i][j] = bias[j] + sum_k x[i][k] * W1[row0+k][j], rows padded to 16.
// ---------------------------------------------------------------------------
__global__ void proj_all(const float* __restrict__ xs, int ns,
                         const float* __restrict__ xt, int nt,
                         const float* __restrict__ uu, int nb,
                         const float* __restrict__ W1,
                         const float* __restrict__ b1,
                         int nbS, int nbT)
{
    int bs = blockIdx.x;
    const float* x; const float* bias = 0; float* out;
    int n, f, row0;
    if (bs < nbS)            { x = xs; n = ns; f = 10; row0 = 0;  out = g_Ps; }
    else if (bs < nbS + nbT) { bs -= nbS; x = xt; n = nt; f = 5;  row0 = 10; out = g_Pt; }
    else                     { bs -= nbS + nbT; x = uu; n = nb; f = 10; row0 = 25; out = g_Pu; bias = b1; }

    __shared__ float sW[10][10];
    __shared__ float sB[10];
    int t = threadIdx.x;
    if (t < f * 10) sW[t / 10][t % 10] = W1[(row0 + t / 10) * 10 + (t % 10)];
    if (t < 10)     sB[t] = bias ? bias[t] : 0.0f;
    __syncthreads();

    int i = bs * blockDim.x + t;
    if (i >= n) return;

    float acc[10];
#pragma unroll
    for (int j = 0; j < 10; j++) acc[j] = sB[j];
    for (int k = 0; k < f; k++) {
        float xv = __ldg(&x[i * f + k]);
#pragma unroll
        for (int j = 0; j < 10; j++) acc[j] = fmaf(xv, sW[k][j], acc[j]);
    }
#pragma unroll
    for (int j = 0; j < 10; j++) out[i * 16 + j] = acc[j];
}

// ---------------------------------------------------------------------------
// Fused edge kernel. Block = 128 threads, tile = 256 edges, 2 edges/thread.
//   P0: stage indices + ea tile (coalesced) into smem
//   P1: cooperative gather, SLOT-MAJOR task order: task = tbl*1280 + s*5 + p.
//       Consecutive lanes read consecutive pairs of the SAME row, so one
//       LDG.64 covers ~6.4 whole rows -> ~1.1 line-touches per gathered row.
//       Lands in sPair[slot*17 + tbl*5 + p] (pad 17 => 2-way LDS conflicts).
//   P2: per-edge packed-f32x2 MLP
//   P3: coalesced float2 store via smem staging
// ---------------------------------------------------------------------------
#define TILE 256
#define NTH  128

__global__ __launch_bounds__(NTH) void edge_kernel(
    const int*   __restrict__ ei,   // [2, E]
    const float* __restrict__ ea,   // [E, 10]
    const int*   __restrict__ be,   // [E]
    const float* __restrict__ W1,   // [35, 10]
    const float* __restrict__ W2,   // [10, 10]
    const float* __restrict__ b2,   // [10]
    float*       __restrict__ out,  // [E, 10]
    int E)
{
    __shared__ u64 sPair[TILE * 17];                 // 34816B: [slot][plane(15) pad 17]
    __shared__ __align__(16) float sW[252];          // W1c 12-pad, W2 12-pad, b2
    __shared__ __align__(16) float sEA[TILE * 10];   // 10240B: ea in / out staging
    __shared__ int sIdx[3 * TILE];                   // 3072B
    // total static smem = 34816 + 1008 + 10240 + 3072 = 49136 B (< 48KB limit)

    int t  = threadIdx.x;
    int e0 = blockIdx.x * TILE;
    int nvalid = E - e0; if (nvalid > TILE) nvalid = TILE;

    // --- weights + b2 into smem (rows padded to 12 floats for LDS.128) ---
    if (t < 120) {
        int k = t / 12, j = t % 12;
        sW[t]       = (j < 10) ? W1[(15 + k) * 10 + j] : 0.0f;
        sW[120 + t] = (j < 10) ? W2[k * 10 + j]        : 0.0f;
    }
    if (t < 10) sW[240 + t] = b2[t];   // FIX: all 10 b2 entries (block is 128 thr)

    // --- P0a: stage indices (clamp invalid slots to edge e0, always valid) ---
    {
        int eA = e0 + t,        cA = (t < nvalid)        ? eA : e0;
        int eB = e0 + t + NTH,  cB = (t + NTH < nvalid)  ? eB : e0;
        sIdx[t]             = ei[cA];      sIdx[t + NTH]        = ei[cB];
        sIdx[TILE + t]      = ei[E + cA];  sIdx[TILE + t + NTH] = ei[E + cB];
        sIdx[2 * TILE + t]  = be[cA];      sIdx[2 * TILE + t + NTH] = be[cB];
    }

    // --- P0b: stage ea tile, coalesced float2 ---
    {
        const float2* g = (const float2*)ea + (size_t)e0 * 5;
        float2* s = (float2*)sEA;
        int npair = nvalid * 5;
#pragma unroll
        for (int i = 0; i < 10; i++) {
            int p = t + NTH * i;
            if (p < npair) s[p] = g[p];
        }
    }
    __syncthreads();

    // --- P1: cooperative gather, slot-major. 3840 u64 tasks, 30 iters.
    //     1280 tasks per table (exactly 10 iterations each, tbl compile-time).
#pragma unroll
    for (int it = 0; it < 30; it++) {
        const int tbl  = it / 10;                    // compile-time
        const float* base = (tbl == 0) ? g_Ps : (tbl == 1) ? g_Pt : g_Pu;
        int task = (it % 10) * NTH + t;              // 0..1279 within table
        int s    = task / 5;                         // slot 0..255
        int p    = task - s * 5;                     // pair 0..4
        int idx  = sIdx[tbl * TILE + s];
        u64 v = *(const u64*)(base + idx * 16 + p * 2);
        sPair[s * 17 + tbl * 5 + p] = v;
    }
    __syncthreads();

    // --- P2: per-edge MLP (2 edges per thread: slots t and t+128) ---
    int sA = t, sB = t + NTH;

    u64 accA[5], accB[5];
#pragma unroll
    for (int j = 0; j < 5; j++) {
        accA[j] = add2(add2(sPair[sA * 17 + j], sPair[sA * 17 + 5 + j]),
                       sPair[sA * 17 + 10 + j]);
        accB[j] = add2(add2(sPair[sB * 17 + j], sPair[sB * 17 + 5 + j]),
                       sPair[sB * 17 + 10 + j]);
    }

    float aA[10], aB[10];
    {
        const float2* s2 = (const float2*)sEA;
#pragma unroll
        for (int m = 0; m < 5; m++) {
            float2 v = s2[sA * 5 + m]; aA[2 * m] = v.x; aA[2 * m + 1] = v.y;
            float2 w = s2[sB * 5 + m]; aB[2 * m] = w.x; aB[2 * m + 1] = w.y;
        }
    }

    // GEMM1: acc += ea @ W1c  (weights broadcast from smem)
#pragma unroll
    for (int k = 0; k < 10; k++) {
        ulonglong2 w01 = *(const ulonglong2*)&sW[k * 12];
        ulonglong2 w23 = *(const ulonglong2*)&sW[k * 12 + 4];
        u64        w4  = *(const u64*)&sW[k * 12 + 8];
        u64 dA = pk2(aA[k], aA[k]);
        u64 dB = pk2(aB[k], aB[k]);
        accA[0] = fma2(dA, w01.x, accA[0]);
        accA[1] = fma2(dA, w01.y, accA[1]);
        accA[2] = fma2(dA, w23.x, accA[2]);
        accA[3] = fma2(dA, w23.y, accA[3]);
        accA[4] = fma2(dA, w4,    accA[4]);
        accB[0] = fma2(dB, w01.x, accB[0]);
        accB[1] = fma2(dB, w01.y, accB[1]);
        accB[2] = fma2(dB, w23.x, accB[2]);
        accB[3] = fma2(dB, w23.y, accB[3]);
        accB[4] = fma2(dB, w4,    accB[4]);
    }

    // leaky_relu(z) = max(z, 0.1z)
    float mA[10], mB[10];
#pragma unroll
    for (int j = 0; j < 5; j++) {
        float z0, z1;
        upk2(accA[j], z0, z1);
        mA[2 * j]     = fmaxf(z0, 0.1f * z0);
        mA[2 * j + 1] = fmaxf(z1, 0.1f * z1);
        upk2(accB[j], z0, z1);
        mB[2 * j]     = fmaxf(z0, 0.1f * z0);
        mB[2 * j + 1] = fmaxf(z1, 0.1f * z1);
    }

    // GEMM2: out = mid @ W2 + b2
    u64 oA[5], oB[5];
    {
        const float2* pb = (const float2*)&sW[240];
#pragma unroll
        for (int j = 0; j < 5; j++) {
            float2 v = pb[j];
            u64 b = pk2(v.x, v.y);
            oA[j] = b; oB[j] = b;
        }
    }
#pragma unroll
    for (int k = 0; k < 10; k++) {
        ulonglong2 w01 = *(const ulonglong2*)&sW[120 + k * 12];
        ulonglong2 w23 = *(const ulonglong2*)&sW[120 + k * 12 + 4];
        u64        w4  = *(const u64*)&sW[120 + k * 12 + 8];
        u64 dA = pk2(mA[k], mA[k]);
        u64 dB = pk2(mB[k], mB[k]);
        oA[0] = fma2(dA, w01.x, oA[0]);
        oA[1] = fma2(dA, w01.y, oA[1]);
        oA[2] = fma2(dA, w23.x, oA[2]);
        oA[3] = fma2(dA, w23.y, oA[3]);
        oA[4] = fma2(dA, w4,    oA[4]);
        oB[0] = fma2(dB, w01.x, oB[0]);
        oB[1] = fma2(dB, w01.y, oB[1]);
        oB[2] = fma2(dB, w23.x, oB[2]);
        oB[3] = fma2(dB, w23.y, oB[3]);
        oB[4] = fma2(dB, w4,    oB[4]);
    }

    // --- P3: stage outputs to smem (reuse sEA), then coalesced store ---
    __syncthreads();   // all ea reads done before overwrite
    {
        float2* so = (float2*)sEA;
#pragma unroll
        for (int j = 0; j < 5; j++) {
            float2 v; upk2(oA[j], v.x, v.y); so[sA * 5 + j] = v;
            float2 w; upk2(oB[j], w.x, w.y); so[sB * 5 + j] = w;
        }
    }
    __syncthreads();
    {
        float2* g = (float2*)out + (size_t)e0 * 5;
        const float2* s = (const float2*)sEA;
        int npair = nvalid * 5;
#pragma unroll
        for (int i = 0; i < 10; i++) {
            int p = t + NTH * i;
            if (p < npair) g[p] = s[p];
        }
    }
}

// ---------------------------------------------------------------------------
// Launch. Inputs (metadata order):
//  0 x_s[N_S,10] f32   1 x_t[N_T,5] f32   2 edge_index[2,E] i32
//  3 edge_attr[E,10] f32   4 u[B,10] f32   5 batch_e[E] i32
//  6 W1[35,10] f32   7 b1[10] f32   8 W2[10,10] f32   9 b2[10] f32
// ---------------------------------------------------------------------------
extern "C" void kernel_launch(void* const* d_in, const int* in_sizes, int n_in,
                              void* d_out, int out_size)
{
    const float* x_s = (const float*)d_in[0];
    const float* x_t = (const float*)d_in[1];
    const int*   ei  = (const int*)  d_in[2];
    const float* ea  = (const float*)d_in[3];
    const float* u   = (const float*)d_in[4];
    const int*   be  = (const int*)  d_in[5];
    const float* W1  = (const float*)d_in[6];
    const float* b1  = (const float*)d_in[7];
    const float* W2  = (const float*)d_in[8];
    const float* b2  = (const float*)d_in[9];
    float* out = (float*)d_out;

    int NS = in_sizes[0] / 10;
    int NT = in_sizes[1] / 5;
    int B  = in_sizes[4] / 10;
    int E  = in_sizes[5];
    if (NS > NS_MAX) NS = NS_MAX;
    if (NT > NT_MAX) NT = NT_MAX;
    if (B  > BB_MAX) B  = BB_MAX;

    // One fused projection launch (W1 rows: x_s 0-9, x_t 10-14, ea 15-24, u 25-34).
    int nbS = (NS + 255) / 256;
    int nbT = (NT + 255) / 256;
    int nbB = (B  + 255) / 256;
    proj_all<<<nbS + nbT + nbB, 256>>>(x_s, NS, x_t, NT, u, B, W1, b1, nbS, nbT);

    // Fused edge MLP: 256-edge tiles, 128 threads, 2 edges/thread.
    int grid = (E + TILE - 1) / TILE;
    edge_kernel<<<grid, NTH>>>(ei, ea, be, W1, W2, b2, out, E);
}

// round 6
// speedup vs baseline: 1.8612x; 1.8612x over previous
#include <cuda_runtime.h>

typedef unsigned long long u64;

// ---------------------------------------------------------------------------
// Static device scratch. Projection tables padded to 16 floats/row (64B) so
// every row lies entirely inside ONE 128B line.
// ---------------------------------------------------------------------------
#define NS_MAX 100000
#define NT_MAX 100000
#define BB_MAX 10000

__device__ __align__(16) float g_Ps[NS_MAX * 16];
__device__ __align__(16) float g_Pt[NT_MAX * 16];
__device__ __align__(16) float g_Pu[BB_MAX * 16];

// ---------------------------------------------------------------------------
// Packed f32x2 helpers (Blackwell sm_103a; ptxas never auto-fuses these).
// ---------------------------------------------------------------------------
__device__ __forceinline__ u64 pk2(float lo, float hi) {
    u64 r; asm("mov.b64 %0, {%1, %2};" : "=l"(r) : "f"(lo), "f"(hi)); return r;
}
__device__ __forceinline__ void upk2(u64 v, float& lo, float& hi) {
    asm("mov.b64 {%0, %1}, %2;" : "=f"(lo), "=f"(hi) : "l"(v));
}
__device__ __forceinline__ u64 fma2(u64 a, u64 b, u64 c) {
    u64 d; asm("fma.rn.f32x2 %0, %1, %2, %3;" : "=l"(d) : "l"(a), "l"(b), "l"(c)); return d;
}
__device__ __forceinline__ u64 add2(u64 a, u64 b) {
    u64 d; asm("add.rn.f32x2 %0, %1, %2;" : "=l"(d) : "l"(a), "l"(b)); return d;
}

// ---------------------------------------------------------------------------
// Fused projection kernel (one launch for all three tables).
// out[i][j] = bias[j] + sum_k x[i][k] * W1[row0+k][j], rows padded to 16.
// ---------------------------------------------------------------------------
__global__ void proj_all(const float* __restrict__ xs, int ns,
                         const float* __restrict__ xt, int nt,
                         const float* __restrict__ uu, int nb,
                         const float* __restrict__ W1,
                         const float* __restrict__ b1,
                         int nbS, int nbT)
{
    int bs = blockIdx.x;
    const float* x; const float* bias = 0; float* out;
    int n, f, row0;
    if (bs < nbS)            { x = xs; n = ns; f = 10; row0 = 0;  out = g_Ps; }
    else if (bs < nbS + nbT) { bs -= nbS; x = xt; n = nt; f = 5;  row0 = 10; out = g_Pt; }
    else                     { bs -= nbS + nbT; x = uu; n = nb; f = 10; row0 = 25; out = g_Pu; bias = b1; }

    __shared__ float sW[10][10];
    __shared__ float sB[10];
    int t = threadIdx.x;
    if (t < f * 10) sW[t / 10][t % 10] = W1[(row0 + t / 10) * 10 + (t % 10)];
    if (t < 10)     sB[t] = bias ? bias[t] : 0.0f;
    __syncthreads();

    int i = bs * blockDim.x + t;
    if (i >= n) return;

    float acc[10];
#pragma unroll
    for (int j = 0; j < 10; j++) acc[j] = sB[j];
    for (int k = 0; k < f; k++) {
        float xv = __ldg(&x[i * f + k]);
#pragma unroll
        for (int j = 0; j < 10; j++) acc[j] = fmaf(xv, sW[k][j], acc[j]);
    }
#pragma unroll
    for (int j = 0; j < 10; j++) out[i * 16 + j] = acc[j];
}

// ---------------------------------------------------------------------------
// Fused edge kernel. 128 threads, tile = 256 edges, 2 edges/thread.
//   P0: stage 3 index arrays (coalesced LDG -> smem)
//   P1: cooperative gather, slot-major tasks (task = s*5 + p): consecutive
//       lanes read consecutive pairs of the SAME row (~1.1 line-touches/row).
//       Each lane sums the pair across ALL THREE tables (3 LDG, 2 add2) and
//       writes ONE u64 to sPair[s*7 + p]  (pad-7 => <=2-way STS/LDS conflicts).
//   P2: per-edge packed-f32x2 MLP; ea loaded directly per-thread; out stored
//       directly per-thread (R3-proven pattern).
// ---------------------------------------------------------------------------
#define TILE 256
#define NTH  128

__global__ __launch_bounds__(NTH) void edge_kernel(
    const int*   __restrict__ ei,   // [2, E]
    const float* __restrict__ ea,   // [E, 10]
    const int*   __restrict__ be,   // [E]
    const float* __restrict__ W1,   // [35, 10]
    const float* __restrict__ W2,   // [10, 10]
    const float* __restrict__ b2,   // [10]
    float*       __restrict__ out,  // [E, 10]
    int E)
{
    __shared__ u64 sPair[TILE * 7];                  // 14336B: summed base pairs
    __shared__ __align__(16) float sW[252];          // W1c 12-pad, W2 12-pad, b2
    __shared__ int sIdx[3 * TILE];                   // 3072B
    // total static smem ~ 18.4KB -> ~5 blocks/SM (reg-limited)

    int t  = threadIdx.x;
    int e0 = blockIdx.x * TILE;
    int nvalid = E - e0; if (nvalid > TILE) nvalid = TILE;

    // --- weights + b2 into smem (rows padded to 12 floats for LDS.128) ---
    if (t < 120) {
        int k = t / 12, j = t % 12;
        sW[t]       = (j < 10) ? W1[(15 + k) * 10 + j] : 0.0f;
        sW[120 + t] = (j < 10) ? W2[k * 10 + j]        : 0.0f;
    }
    if (t < 10) sW[240 + t] = b2[t];

    // --- P0: stage indices (clamp invalid slots to edge e0, always valid) ---
    {
        int eA = e0 + t,        cA = (t < nvalid)        ? eA : e0;
        int eB = e0 + t + NTH,  cB = (t + NTH < nvalid)  ? eB : e0;
        sIdx[t]             = ei[cA];      sIdx[t + NTH]        = ei[cB];
        sIdx[TILE + t]      = ei[E + cA];  sIdx[TILE + t + NTH] = ei[E + cB];
        sIdx[2 * TILE + t]  = be[cA];      sIdx[2 * TILE + t + NTH] = be[cB];
    }
    __syncthreads();

    // --- P1: cooperative gather + 3-table sum. 1280 tasks, 10 iterations. ---
#pragma unroll
    for (int it = 0; it < 10; it++) {
        int task = it * NTH + t;             // 0..1279
        int s    = task / 5;                 // slot 0..255 (mul-shift)
        int p    = task - s * 5;             // pair 0..4
        int i0 = sIdx[s];
        int i1 = sIdx[TILE + s];
        int i2 = sIdx[2 * TILE + s];
        u64 v0 = *(const u64*)(g_Ps + i0 * 16 + p * 2);
        u64 v1 = *(const u64*)(g_Pt + i1 * 16 + p * 2);
        u64 v2 = *(const u64*)(g_Pu + i2 * 16 + p * 2);
        sPair[s * 7 + p] = add2(add2(v0, v1), v2);
    }
    __syncthreads();

    // --- P2: per-edge MLP (2 edges per thread: slots t and t+128) ---
    int sA = t, sB = t + NTH;
    int eA = e0 + sA, eB = e0 + sB;
    int ecA = (sA < nvalid) ? eA : e0;
    int ecB = (sB < nvalid) ? eB : e0;

    u64 accA[5], accB[5];
#pragma unroll
    for (int j = 0; j < 5; j++) {
        accA[j] = sPair[sA * 7 + j];
        accB[j] = sPair[sB * 7 + j];
    }

    // ea loaded directly (float2 x5 per edge; rows are 8B-aligned)
    float aA[10], aB[10];
    {
        const float2* pA = (const float2*)ea + (size_t)ecA * 5;
        const float2* pB = (const float2*)ea + (size_t)ecB * 5;
#pragma unroll
        for (int m = 0; m < 5; m++) {
            float2 v = pA[m]; aA[2 * m] = v.x; aA[2 * m + 1] = v.y;
            float2 w = pB[m]; aB[2 * m] = w.x; aB[2 * m + 1] = w.y;
        }
    }

    // GEMM1: acc += ea @ W1c  (weights broadcast from smem, shared by 2 edges)
#pragma unroll
    for (int k = 0; k < 10; k++) {
        ulonglong2 w01 = *(const ulonglong2*)&sW[k * 12];
        ulonglong2 w23 = *(const ulonglong2*)&sW[k * 12 + 4];
        u64        w4  = *(const u64*)&sW[k * 12 + 8];
        u64 dA = pk2(aA[k], aA[k]);
        u64 dB = pk2(aB[k], aB[k]);
        accA[0] = fma2(dA, w01.x, accA[0]);
        accA[1] = fma2(dA, w01.y, accA[1]);
        accA[2] = fma2(dA, w23.x, accA[2]);
        accA[3] = fma2(dA, w23.y, accA[3]);
        accA[4] = fma2(dA, w4,    accA[4]);
        accB[0] = fma2(dB, w01.x, accB[0]);
        accB[1] = fma2(dB, w01.y, accB[1]);
        accB[2] = fma2(dB, w23.x, accB[2]);
        accB[3] = fma2(dB, w23.y, accB[3]);
        accB[4] = fma2(dB, w4,    accB[4]);
    }

    // leaky_relu(z) = max(z, 0.1z)
    float mA[10], mB[10];
#pragma unroll
    for (int j = 0; j < 5; j++) {
        float z0, z1;
        upk2(accA[j], z0, z1);
        mA[2 * j]     = fmaxf(z0, 0.1f * z0);
        mA[2 * j + 1] = fmaxf(z1, 0.1f * z1);
        upk2(accB[j], z0, z1);
        mB[2 * j]     = fmaxf(z0, 0.1f * z0);
        mB[2 * j + 1] = fmaxf(z1, 0.1f * z1);
    }

    // GEMM2: out = mid @ W2 + b2
    u64 oA[5], oB[5];
    {
        const float2* pb = (const float2*)&sW[240];
#pragma unroll
        for (int j = 0; j < 5; j++) {
            float2 v = pb[j];
            u64 b = pk2(v.x, v.y);
            oA[j] = b; oB[j] = b;
        }
    }
#pragma unroll
    for (int k = 0; k < 10; k++) {
        ulonglong2 w01 = *(const ulonglong2*)&sW[120 + k * 12];
        ulonglong2 w23 = *(const ulonglong2*)&sW[120 + k * 12 + 4];
        u64        w4  = *(const u64*)&sW[120 + k * 12 + 8];
        u64 dA = pk2(mA[k], mA[k]);
        u64 dB = pk2(mB[k], mB[k]);
        oA[0] = fma2(dA, w01.x, oA[0]);
        oA[1] = fma2(dA, w01.y, oA[1]);
        oA[2] = fma2(dA, w23.x, oA[2]);
        oA[3] = fma2(dA, w23.y, oA[3]);
        oA[4] = fma2(dA, w4,    oA[4]);
        oB[0] = fma2(dB, w01.x, oB[0]);
        oB[1] = fma2(dB, w01.y, oB[1]);
        oB[2] = fma2(dB, w23.x, oB[2]);
        oB[3] = fma2(dB, w23.y, oB[3]);
        oB[4] = fma2(dB, w4,    oB[4]);
    }

    // --- direct stores (guarded) ---
    if (sA < nvalid) {
        float2* O = (float2*)(out + (size_t)eA * 10);
#pragma unroll
        for (int j = 0; j < 5; j++) { float2 v; upk2(oA[j], v.x, v.y); O[j] = v; }
    }
    if (sB < nvalid) {
        float2* O = (float2*)(out + (size_t)eB * 10);
#pragma unroll
        for (int j = 0; j < 5; j++) { float2 v; upk2(oB[j], v.x, v.y); O[j] = v; }
    }
}

// ---------------------------------------------------------------------------
// Launch. Inputs (metadata order):
//  0 x_s[N_S,10] f32   1 x_t[N_T,5] f32   2 edge_index[2,E] i32
//  3 edge_attr[E,10] f32   4 u[B,10] f32   5 batch_e[E] i32
//  6 W1[35,10] f32   7 b1[10] f32   8 W2[10,10] f32   9 b2[10] f32
// ---------------------------------------------------------------------------
extern "C" void kernel_launch(void* const* d_in, const int* in_sizes, int n_in,
                              void* d_out, int out_size)
{
    const float* x_s = (const float*)d_in[0];
    const float* x_t = (const float*)d_in[1];
    const int*   ei  = (const int*)  d_in[2];
    const float* ea  = (const float*)d_in[3];
    const float* u   = (const float*)d_in[4];
    const int*   be  = (const int*)  d_in[5];
    const float* W1  = (const float*)d_in[6];
    const float* b1  = (const float*)d_in[7];
    const float* W2  = (const float*)d_in[8];
    const float* b2  = (const float*)d_in[9];
    float* out = (float*)d_out;

    int NS = in_sizes[0] / 10;
    int NT = in_sizes[1] / 5;
    int B  = in_sizes[4] / 10;
    int E  = in_sizes[5];
    if (NS > NS_MAX) NS = NS_MAX;
    if (NT > NT_MAX) NT = NT_MAX;
    if (B  > BB_MAX) B  = BB_MAX;

    // One fused projection launch (W1 rows: x_s 0-9, x_t 10-14, ea 15-24, u 25-34).
    int nbS = (NS + 255) / 256;
    int nbT = (NT + 255) / 256;
    int nbB = (B  + 255) / 256;
    proj_all<<<nbS + nbT + nbB, 256>>>(x_s, NS, x_t, NT, u, B, W1, b1, nbS, nbT);

    // Fused edge MLP: 256-edge tiles, 128 threads, 2 edges/thread.
    int grid = (E + TILE - 1) / TILE;
    edge_kernel<<<grid, NTH>>>(ei, ea, be, W1, W2, b2, out, E);
}